// round 6
// baseline (speedup 1.0000x reference)
#include <cuda_runtime.h>
#include <float.h>

// Shapes (fixed by the problem): B=32, S=4096, H=1024, K=2
#define B_ 32
#define S_ 4096
#define H_ 1024
#define K_ 2

#define THREADS 256
#define WARPS_PER_BLOCK (THREADS/32)
#define FCHUNK 32                   // features per warp (8 lanes * float4)
#define WCHUNKS (H_/FCHUNK)         // 32 warps per (b,k)
#define RGROUPS 4                   // row groups per warp
#define LOADS 16                    // rows per thread (4*16 = 64 rows covered)

__device__ __forceinline__ float4 f4max(float4 a, float4 b) {
    float4 r;
    r.x = fmaxf(a.x, b.x);
    r.y = fmaxf(a.y, b.y);
    r.z = fmaxf(a.z, b.z);
    r.w = fmaxf(a.w, b.w);
    return r;
}

__global__ void __launch_bounds__(THREADS)
span_max_kernel(const float* __restrict__ hs,   // [B, S, H]
                const int* __restrict__ st,     // [B, K] (int32)
                const int* __restrict__ en,     // [B, K]
                const float* __restrict__ me,   // [K, H]
                float* __restrict__ out)        // [B, K*H]
{
    const int lane = threadIdx.x & 31;
    const int gw   = blockIdx.x * WARPS_PER_BLOCK + (threadIdx.x >> 5); // global warp

    // decompose: gw -> (b, k, feature chunk)
    const int b  = gw / (K_ * WCHUNKS);
    const int rm = gw % (K_ * WCHUNKS);
    const int k  = rm / WCHUNKS;
    const int wc = rm % WCHUNKS;

    const int lf = lane & 7;        // feature lane within warp
    const int g  = lane >> 3;       // row group 0..3

    const int f = wc * FCHUNK + lf * 4;   // feature offset

    const int s_raw = __ldg(&st[b * K_ + k]);
    const int e_raw = __ldg(&en[b * K_ + k]);

    float* op = out + (size_t)b * (K_ * H_) + (size_t)k * H_ + f;

    if (s_raw < 0 || e_raw < 0) {
        // missing: copy missing_embeddings[k] (uniform across warp — no divergence)
        if (g == 0) {
            float4 v = *reinterpret_cast<const float4*>(me + (size_t)k * H_ + f);
            *reinterpret_cast<float4*>(op) = v;
        }
        return;
    }

    // defensive clamps: keep every generated row index inside [0, S)
    const int s  = s_raw < S_ ? s_raw : (S_ - 1);
    const int e  = e_raw < S_ ? e_raw : S_;
    const int el = e - 1;           // last valid row (length >= 1 by construction)

    const float* base = hs + ((size_t)b * S_) * H_ + f;

    // 16 independent, unpredicated loads per thread; row index clamped to the
    // span's last row. Rows covered: s + g + 4*j, g in [0,4), j in [0,16)
    // => s .. s+63 (span length < 64). One latency wait, MLP=16.
    float4 v[LOADS];
    #pragma unroll
    for (int j = 0; j < LOADS; j++) {
        int r = s + g + RGROUPS * j;
        r = r < el ? r : el;
        v[j] = *reinterpret_cast<const float4*>(base + (size_t)r * H_);
    }

    float4 m = v[0];
    #pragma unroll
    for (int j = 1; j < LOADS; j++)
        m = f4max(m, v[j]);

    // generic-safety tail for spans >= 64 rows (never taken for this problem)
    for (int r = s + g + RGROUPS * LOADS; r < e; r += RGROUPS) {
        float4 a = *reinterpret_cast<const float4*>(base + (size_t)r * H_);
        m = f4max(m, a);
    }

    // combine the 4 row groups across the warp: lanes differing in bits 3,4
    #pragma unroll
    for (int off = 8; off <= 16; off <<= 1) {
        m.x = fmaxf(m.x, __shfl_xor_sync(0xffffffffu, m.x, off));
        m.y = fmaxf(m.y, __shfl_xor_sync(0xffffffffu, m.y, off));
        m.z = fmaxf(m.z, __shfl_xor_sync(0xffffffffu, m.z, off));
        m.w = fmaxf(m.w, __shfl_xor_sync(0xffffffffu, m.w, off));
    }

    if (g == 0)
        *reinterpret_cast<float4*>(op) = m;
}

extern "C" void kernel_launch(void* const* d_in, const int* in_sizes, int n_in,
                              void* d_out, int out_size) {
    const float* hs  = (const float*)d_in[0];
    const int*   st  = (const int*)d_in[1];
    const int*   en  = (const int*)d_in[2];
    const float* me  = (const float*)d_in[3];
    float*       out = (float*)d_out;

    // 2048 warps total = 256 blocks x 256 threads, single wave on 148 SMs
    dim3 grid(B_ * K_ * WCHUNKS / WARPS_PER_BLOCK);
    span_max_kernel<<<grid, THREADS>>>(hs, st, en, me, out);
}

// round 7
// speedup vs baseline: 1.0047x; 1.0047x over previous
#include <cuda_runtime.h>
#include <float.h>

// Shapes (fixed by the problem): B=32, S=4096, H=1024, K=2
#define B_ 32
#define S_ 4096
#define H_ 1024
#define K_ 2

#define LANES   64                 // feature lanes per block (float4 each)
#define GROUPS  16                 // row groups per block
#define THREADS (LANES*GROUPS)     // 1024
#define CHUNK   (LANES*4)          // 256 features per block
#define CHUNKS  (H_/CHUNK)         // 4

__device__ __forceinline__ float4 f4max(float4 a, float4 b) {
    float4 r;
    r.x = fmaxf(a.x, b.x);
    r.y = fmaxf(a.y, b.y);
    r.z = fmaxf(a.z, b.z);
    r.w = fmaxf(a.w, b.w);
    return r;
}

__global__ void __launch_bounds__(THREADS)
span_max_kernel(const float* __restrict__ hs,   // [B, S, H]
                const int* __restrict__ st,     // [B, K] (int32)
                const int* __restrict__ en,     // [B, K]
                const float* __restrict__ me,   // [K, H]
                float* __restrict__ out)        // [B, K*H]
{
    __shared__ float4 part[GROUPS][LANES];

    const int blk   = blockIdx.x;
    const int chunk = blk % CHUNKS;
    const int bk    = blk / CHUNKS;
    const int b     = bk / K_;
    const int k     = bk % K_;

    const int lane = threadIdx.x & (LANES - 1);
    const int g    = threadIdx.x / LANES;

    const int f = chunk * CHUNK + lane * 4;     // feature offset

    const int s_raw = __ldg(&st[b * K_ + k]);
    const int e_raw = __ldg(&en[b * K_ + k]);

    float* op = out + (size_t)b * (K_ * H_) + (size_t)k * H_ + f;

    if (s_raw < 0 || e_raw < 0) {
        // missing: copy missing_embeddings[k]; all threads return (no syncs follow)
        if (g == 0) {
            float4 v = *reinterpret_cast<const float4*>(me + (size_t)k * H_ + f);
            *reinterpret_cast<float4*>(op) = v;
        }
        return;
    }

    // defensive clamps: keep every generated row index inside [0, S)
    const int s  = s_raw < S_ ? s_raw : (S_ - 1);
    const int e  = e_raw < S_ ? e_raw : S_;
    const int el = e - 1;                       // last valid row (length >= 1)

    const float* base = hs + ((size_t)b * S_) * H_ + f;

    // 4 independent UNPREDICATED loads per thread, row index clamped to the
    // span's last row (duplicate reads of row el are harmless for max and hit
    // lines already in flight). Rows covered: s+g+16j, g in [0,16), j in [0,4)
    // => s .. s+63 (span length < 64). One latency wait, MLP=4 per thread
    // (x32 warps per block in flight).
    int r0 = s + g;
    int r1 = r0 + 1 * GROUPS;
    int r2 = r0 + 2 * GROUPS;
    int r3 = r0 + 3 * GROUPS;
    r0 = r0 < el ? r0 : el;
    r1 = r1 < el ? r1 : el;
    r2 = r2 < el ? r2 : el;
    r3 = r3 < el ? r3 : el;

    float4 a0 = *reinterpret_cast<const float4*>(base + (size_t)r0 * H_);
    float4 a1 = *reinterpret_cast<const float4*>(base + (size_t)r1 * H_);
    float4 a2 = *reinterpret_cast<const float4*>(base + (size_t)r2 * H_);
    float4 a3 = *reinterpret_cast<const float4*>(base + (size_t)r3 * H_);
    float4 m  = f4max(f4max(a0, a1), f4max(a2, a3));

    // generic-safety tail for spans >= 64 rows (never taken for this problem)
    for (int r = s + g + 4 * GROUPS; r < e; r += GROUPS) {
        float4 a = *reinterpret_cast<const float4*>(base + (size_t)r * H_);
        m = f4max(m, a);
    }

    part[g][lane] = m;
    __syncthreads();

    if (g == 0) {
        // 15 independent LDS.128 + fmax tree
        float4 acc = part[0][lane];
        #pragma unroll
        for (int i = 1; i < GROUPS; i++)
            acc = f4max(acc, part[i][lane]);
        *reinterpret_cast<float4*>(op) = acc;
    }
}

extern "C" void kernel_launch(void* const* d_in, const int* in_sizes, int n_in,
                              void* d_out, int out_size) {
    const float* hs  = (const float*)d_in[0];
    const int*   st  = (const int*)d_in[1];
    const int*   en  = (const int*)d_in[2];
    const float* me  = (const float*)d_in[3];
    float*       out = (float*)d_out;

    dim3 grid(B_ * K_ * CHUNKS);   // 256 blocks x 1024 threads, single wave
    span_max_kernel<<<grid, THREADS>>>(hs, st, en, me, out);
}

// round 8
// speedup vs baseline: 1.0385x; 1.0337x over previous
#include <cuda_runtime.h>
#include <float.h>

// Shapes (fixed by the problem): B=32, S=4096, H=1024, K=2
#define B_ 32
#define S_ 4096
#define H_ 1024
#define K_ 2

#define LANES   64                 // feature lanes per unit (float4 each)
#define GROUPS  16                 // row groups per block
#define THREADS (LANES*GROUPS)     // 1024
#define UNIT    (LANES*4)          // 256 features per unit
#define UNITS   2                  // units per block
#define CHUNK   (UNIT*UNITS)       // 512 features per block
#define CHUNKS  (H_/CHUNK)         // 2

__device__ __forceinline__ float4 f4max(float4 a, float4 b) {
    float4 r;
    r.x = fmaxf(a.x, b.x);
    r.y = fmaxf(a.y, b.y);
    r.z = fmaxf(a.z, b.z);
    r.w = fmaxf(a.w, b.w);
    return r;
}

__global__ void __launch_bounds__(THREADS)
span_max_kernel(const float* __restrict__ hs,   // [B, S, H]
                const int* __restrict__ st,     // [B, K] (int32)
                const int* __restrict__ en,     // [B, K]
                const float* __restrict__ me,   // [K, H]
                float* __restrict__ out)        // [B, K*H]
{
    __shared__ float4 part[UNITS][GROUPS][LANES];

    const int blk   = blockIdx.x;
    const int chunk = blk % CHUNKS;
    const int bk    = blk / CHUNKS;
    const int b     = bk / K_;
    const int k     = bk % K_;

    const int lane = threadIdx.x & (LANES - 1);
    const int g    = threadIdx.x / LANES;

    // feature offsets for the two units this thread serves
    const int f0 = chunk * CHUNK + lane * 4;          // unit 0
    const int f1 = f0 + UNIT;                         // unit 1

    const int s_raw = __ldg(&st[b * K_ + k]);
    const int e_raw = __ldg(&en[b * K_ + k]);

    float* op = out + (size_t)b * (K_ * H_) + (size_t)k * H_;

    if (s_raw < 0 || e_raw < 0) {
        // missing: copy missing_embeddings[k]; all threads return (no syncs follow)
        if (g == 0) {
            float4 v0 = *reinterpret_cast<const float4*>(me + (size_t)k * H_ + f0);
            float4 v1 = *reinterpret_cast<const float4*>(me + (size_t)k * H_ + f1);
            *reinterpret_cast<float4*>(op + f0) = v0;
            *reinterpret_cast<float4*>(op + f1) = v1;
        }
        return;
    }

    // defensive clamps: never index outside [0, S)
    const int s = s_raw < S_ ? s_raw : S_;
    const int e = e_raw < S_ ? e_raw : S_;

    const float* base0 = hs + ((size_t)b * S_) * H_ + f0;
    const float* base1 = hs + ((size_t)b * S_) * H_ + f1;

    const float4 NEG = make_float4(-FLT_MAX, -FLT_MAX, -FLT_MAX, -FLT_MAX);

    // rows covered: s+g+16j, j in [0,4) => s..s+63 (span < 64).
    // 8 independent PREDICATED loads (4 rows x 2 units), issued back-to-back:
    // one latency wait, MLP=8 per thread, zero duplicate traffic.
    const int r0 = s + g;
    const int r1 = r0 + GROUPS;
    const int r2 = r0 + 2 * GROUPS;
    const int r3 = r0 + 3 * GROUPS;

    float4 u0a0 = (r0 < e) ? *reinterpret_cast<const float4*>(base0 + (size_t)r0 * H_) : NEG;
    float4 u1a0 = (r0 < e) ? *reinterpret_cast<const float4*>(base1 + (size_t)r0 * H_) : NEG;
    float4 u0a1 = (r1 < e) ? *reinterpret_cast<const float4*>(base0 + (size_t)r1 * H_) : NEG;
    float4 u1a1 = (r1 < e) ? *reinterpret_cast<const float4*>(base1 + (size_t)r1 * H_) : NEG;
    float4 u0a2 = (r2 < e) ? *reinterpret_cast<const float4*>(base0 + (size_t)r2 * H_) : NEG;
    float4 u1a2 = (r2 < e) ? *reinterpret_cast<const float4*>(base1 + (size_t)r2 * H_) : NEG;
    float4 u0a3 = (r3 < e) ? *reinterpret_cast<const float4*>(base0 + (size_t)r3 * H_) : NEG;
    float4 u1a3 = (r3 < e) ? *reinterpret_cast<const float4*>(base1 + (size_t)r3 * H_) : NEG;

    float4 m0 = f4max(f4max(u0a0, u0a1), f4max(u0a2, u0a3));
    float4 m1 = f4max(f4max(u1a0, u1a1), f4max(u1a2, u1a3));

    // generic-safety tail for spans >= 64 rows (never taken for this problem)
    for (int r = r0 + 4 * GROUPS; r < e; r += GROUPS) {
        m0 = f4max(m0, *reinterpret_cast<const float4*>(base0 + (size_t)r * H_));
        m1 = f4max(m1, *reinterpret_cast<const float4*>(base1 + (size_t)r * H_));
    }

    part[0][g][lane] = m0;
    part[1][g][lane] = m1;
    __syncthreads();

    if (g == 0) {
        float4 acc0 = part[0][0][lane];
        float4 acc1 = part[1][0][lane];
        #pragma unroll
        for (int i = 1; i < GROUPS; i++) {
            acc0 = f4max(acc0, part[0][i][lane]);
            acc1 = f4max(acc1, part[1][i][lane]);
        }
        *reinterpret_cast<float4*>(op + f0) = acc0;
        *reinterpret_cast<float4*>(op + f1) = acc1;
    }
}

extern "C" void kernel_launch(void* const* d_in, const int* in_sizes, int n_in,
                              void* d_out, int out_size) {
    const float* hs  = (const float*)d_in[0];
    const int*   st  = (const int*)d_in[1];
    const int*   en  = (const int*)d_in[2];
    const float* me  = (const float*)d_in[3];
    float*       out = (float*)d_out;

    dim3 grid(B_ * K_ * CHUNKS);   // 128 blocks x 1024 threads, <=1 CTA/SM
    span_max_kernel<<<grid, THREADS>>>(hs, st, en, me, out);
}

// round 9
// speedup vs baseline: 1.0435x; 1.0048x over previous
#include <cuda_runtime.h>
#include <float.h>

// Shapes (fixed by the problem): B=32, S=4096, H=1024, K=2
#define B_ 32
#define S_ 4096
#define H_ 1024
#define K_ 2

#define LANES   64                 // feature lanes per block (float4 each)
#define GROUPS  16                 // row groups per block
#define THREADS (LANES*GROUPS)     // 1024
#define CHUNK   (LANES*4)          // 256 features per block
#define CHUNKS  (H_/CHUNK)         // 4

__device__ __forceinline__ float4 f4max(float4 a, float4 b) {
    float4 r;
    r.x = fmaxf(a.x, b.x);
    r.y = fmaxf(a.y, b.y);
    r.z = fmaxf(a.z, b.z);
    r.w = fmaxf(a.w, b.w);
    return r;
}

__global__ void __launch_bounds__(THREADS)
span_max_kernel(const float* __restrict__ hs,   // [B, S, H]
                const int* __restrict__ st,     // [B, K] (int32)
                const int* __restrict__ en,     // [B, K]
                const float* __restrict__ me,   // [K, H]
                float* __restrict__ out)        // [B, K*H]
{
    __shared__ float4 part[GROUPS][LANES];

    const int blk   = blockIdx.x;
    const int chunk = blk % CHUNKS;
    const int bk    = blk / CHUNKS;
    const int b     = bk / K_;
    const int k     = bk % K_;

    const int lane = threadIdx.x & (LANES - 1);
    const int g    = threadIdx.x / LANES;

    const int f = chunk * CHUNK + lane * 4;     // feature offset

    const int s_raw = __ldg(&st[b * K_ + k]);
    const int e_raw = __ldg(&en[b * K_ + k]);

    float* op = out + (size_t)b * (K_ * H_) + (size_t)k * H_ + f;

    if (s_raw < 0 || e_raw < 0) {
        // missing: copy missing_embeddings[k]; uniform branch, all threads
        // return without touching the named barrier.
        if (g == 0) {
            float4 v = *reinterpret_cast<const float4*>(me + (size_t)k * H_ + f);
            *reinterpret_cast<float4*>(op) = v;
        }
        return;
    }

    // defensive clamps: never index outside [0, S)
    const int s = s_raw < S_ ? s_raw : S_;
    const int e = e_raw < S_ ? e_raw : S_;

    const float* base = hs + ((size_t)b * S_) * H_ + f;

    const float4 NEG = make_float4(-FLT_MAX, -FLT_MAX, -FLT_MAX, -FLT_MAX);

    // rows covered: s+g+16j, j in [0,4) => s..s+63 (span length < 64).
    // 4 independent PREDICATED loads per thread (no duplicate traffic),
    // issued back-to-back: one latency wait.
    const int r0 = s + g;
    const int r1 = r0 + GROUPS;
    const int r2 = r0 + 2 * GROUPS;
    const int r3 = r0 + 3 * GROUPS;

    float4 a0 = (r0 < e) ? *reinterpret_cast<const float4*>(base + (size_t)r0 * H_) : NEG;
    float4 a1 = (r1 < e) ? *reinterpret_cast<const float4*>(base + (size_t)r1 * H_) : NEG;
    float4 a2 = (r2 < e) ? *reinterpret_cast<const float4*>(base + (size_t)r2 * H_) : NEG;
    float4 a3 = (r3 < e) ? *reinterpret_cast<const float4*>(base + (size_t)r3 * H_) : NEG;
    float4 m  = f4max(f4max(a0, a1), f4max(a2, a3));

    // generic-safety tail for spans >= 64 rows (never taken for this problem)
    for (int r = r0 + 4 * GROUPS; r < e; r += GROUPS) {
        float4 a = *reinterpret_cast<const float4*>(base + (size_t)r * H_);
        m = f4max(m, a);
    }

    part[g][lane] = m;

    // Asymmetric barrier: producer groups (g>0) arrive and EXIT immediately,
    // freeing 30/32 warps off the SM; only group 0's two warps block, then
    // reduce and store. bar.arrive/bar.sync pair on named barrier 1 with the
    // full 1024-thread count.
    if (g != 0) {
        asm volatile("bar.arrive 1, %0;" :: "r"(THREADS) : "memory");
        return;
    }
    asm volatile("bar.sync 1, %0;" :: "r"(THREADS) : "memory");

    // 15 independent LDS.128 + fmax tree
    float4 acc = part[0][lane];
    #pragma unroll
    for (int i = 1; i < GROUPS; i++)
        acc = f4max(acc, part[i][lane]);
    *reinterpret_cast<float4*>(op) = acc;
}

extern "C" void kernel_launch(void* const* d_in, const int* in_sizes, int n_in,
                              void* d_out, int out_size) {
    const float* hs  = (const float*)d_in[0];
    const int*   st  = (const int*)d_in[1];
    const int*   en  = (const int*)d_in[2];
    const float* me  = (const float*)d_in[3];
    float*       out = (float*)d_out;

    dim3 grid(B_ * K_ * CHUNKS);   // 256 blocks x 1024 threads, single wave
    span_max_kernel<<<grid, THREADS>>>(hs, st, en, me, out);
}